// round 11
// baseline (speedup 1.0000x reference)
#include <cuda_runtime.h>
#include <cuda_fp16.h>
#include <cstdint>

// CoreSageLayer, fp16 HMMA (sm_103-base PTX):
//   out[k] = concat((adj@x)/deg, x) @ W[k] + bias
// prep_split : x -> xT fp16 (stage-1 B) + n_x right half (fp16 x)
// prep_w     : W -> W^T fp16
// sage_agg   : part[z] = adj[:, zK:] @ xT, fp32 acc, BK=64,
//              CTA 64x256, 8 warps (32x64), 2 CTAs/SM, grid (128, 2)
// sage_combine: n_x left half = (p0+p1)/deg  (fp16)
// sage_out   : out = n_x @ W^T + bias; tile 128x128, 2 CTAs/SM

#define N_NODES 8192
#define IN_F    256
#define TWO_F   512
#define OUT_F   256
#define ROWB    144          // 64 fp16 + 8 pad = 144 bytes

__device__ __half g_xT[(size_t)IN_F * N_NODES];
__device__ __half g_nx[(size_t)N_NODES * TWO_F];
__device__ __half g_wT[3u * OUT_F * TWO_F];
__device__ float  g_part[2ull * N_NODES * IN_F];
__device__ float  g_degp[2 * N_NODES];

__device__ __forceinline__ uint32_t smem_u32(const void* p) {
    uint32_t a;
    asm("{ .reg .u64 t; cvta.to.shared.u64 t, %1; cvt.u32.u64 %0, t; }"
        : "=r"(a) : "l"(p));
    return a;
}
#define LDMX4(r, addr) \
    asm volatile("ldmatrix.sync.aligned.m8n8.x4.shared.b16 {%0,%1,%2,%3}, [%4];" \
        : "=r"((r)[0]), "=r"((r)[1]), "=r"((r)[2]), "=r"((r)[3]) : "r"(addr))
#define MMA(d, a, b0, b1) \
    asm volatile("mma.sync.aligned.m16n8k16.row.col.f32.f16.f16.f32 " \
        "{%0,%1,%2,%3}, {%4,%5,%6,%7}, {%8,%9}, {%0,%1,%2,%3};" \
        : "+f"((d)[0]), "+f"((d)[1]), "+f"((d)[2]), "+f"((d)[3]) \
        : "r"((a)[0]), "r"((a)[1]), "r"((a)[2]), "r"((a)[3]), "r"(b0), "r"(b1))
#define CP16(dst, src) \
    asm volatile("cp.async.cg.shared.global [%0], [%1], 16;" \
        :: "r"(dst), "l"(src) : "memory")
#define CPCOMMIT()  asm volatile("cp.async.commit_group;" ::: "memory")
#define CPWAITALL() asm volatile("cp.async.wait_group 0;" ::: "memory")
#define STS128U(addr, v) \
    asm volatile("st.shared.v4.b32 [%0], {%1,%2,%3,%4};" \
        :: "r"(addr), "r"((v).x), "r"((v).y), "r"((v).z), "r"((v).w) : "memory")

// =================== prep: x -> xT fp16, + n_x right half ===================
__global__ void prep_split(const float* __restrict__ x) {
    __shared__ float t[32][33];
    const int tx = threadIdx.x, ty = threadIdx.y;
    const int k0 = blockIdx.x * 32, n0 = blockIdx.y * 32;
#pragma unroll
    for (int i = 0; i < 32; i += 8) {
        const float v = x[(size_t)(k0 + ty + i) * IN_F + n0 + tx];
        t[ty + i][tx] = v;
        g_nx[(size_t)(k0 + ty + i) * TWO_F + IN_F + n0 + tx] = __float2half_rn(v);
    }
    __syncthreads();
#pragma unroll
    for (int i = 0; i < 32; i += 8)
        g_xT[(size_t)(n0 + ty + i) * N_NODES + k0 + tx] =
            __float2half_rn(t[tx][ty + i]);
}

// =================== prep: W -> W^T fp16 ===================
__global__ void prep_w(const float* __restrict__ w) {
    __shared__ float t[32][33];
    const int tx = threadIdx.x, ty = threadIdx.y;
    const int f0 = blockIdx.x * 32, o0 = blockIdx.y * 32, h = blockIdx.z;
    const float* wk = w + (size_t)h * TWO_F * OUT_F;
#pragma unroll
    for (int i = 0; i < 32; i += 8)
        t[ty + i][tx] = wk[(size_t)(f0 + ty + i) * OUT_F + o0 + tx];
    __syncthreads();
#pragma unroll
    for (int i = 0; i < 32; i += 8)
        g_wT[((size_t)h * OUT_F + o0 + ty + i) * TWO_F + f0 + tx] =
            __float2half_rn(t[tx][ty + i]);
}

// =================== Stage 1: adj aggregate (64x256, 2 CTAs/SM) ==========
// A buf 64x144 = 9216, B buf 256x144 = 36864; double buffered = 92160 B.
#define S1_A0   0u
#define S1_A1   9216u
#define S1_B0   18432u
#define S1_B1   55296u
#define S1_SMEM 92160

__global__ __launch_bounds__(256, 2)
void sage_agg(const int* __restrict__ adj)
{
    extern __shared__ char smem[];
    const uint32_t sb = smem_u32(smem);
    const int tid = threadIdx.x, lane = tid & 31, wid = tid >> 5;
    const int wy = wid & 1, wx = wid >> 1;       // 2 x 4 warps, 32m x 64n
    const int rb  = blockIdx.x * 64;
    const int z   = blockIdx.y;
    const int kzb = z * (N_NODES / 2);
    const int T   = (N_NODES / 2) / 64;          // 64 chunks

    const int arow = tid >> 2, aseg = tid & 3;   // 4 thr per A row (64 ints)
    // B: 1 thread per row (256 rows), 128 B each
    const int*    aptr = adj + (size_t)(rb + arow) * N_NODES + kzb + aseg * 16;
    const __half* bsrc = g_xT + (size_t)tid * N_NODES + kzb;

    const uint32_t a_sts = (uint32_t)(arow * ROWB + aseg * 32);
    const uint32_t b_sts = (uint32_t)(tid * ROWB);
    const uint32_t aoff[2] = {S1_A0, S1_A1};
    const uint32_t boff[2] = {S1_B0, S1_B1};

    const uint32_t a_ld = (uint32_t)((wy * 32 + (lane & 15)) * ROWB) + (lane & 16);
    const uint32_t b_ld = (uint32_t)((wx * 64 + (lane & 15)) * ROWB) + (lane & 16);

    float acc[2][8][4];
#pragma unroll
    for (int i = 0; i < 2; i++)
#pragma unroll
        for (int j = 0; j < 8; j++)
#pragma unroll
            for (int k = 0; k < 4; k++) acc[i][j][k] = 0.0f;

    int deg = 0;

    auto cvt_sts = [&](const int4* v, uint32_t dstA) {
        uint4 o1, o2;
        o1.x = (uint32_t)v[0].x * 0x3C00u + (uint32_t)v[0].y * 0x3C000000u;
        o1.y = (uint32_t)v[0].z * 0x3C00u + (uint32_t)v[0].w * 0x3C000000u;
        o1.z = (uint32_t)v[1].x * 0x3C00u + (uint32_t)v[1].y * 0x3C000000u;
        o1.w = (uint32_t)v[1].z * 0x3C00u + (uint32_t)v[1].w * 0x3C000000u;
        o2.x = (uint32_t)v[2].x * 0x3C00u + (uint32_t)v[2].y * 0x3C000000u;
        o2.y = (uint32_t)v[2].z * 0x3C00u + (uint32_t)v[2].w * 0x3C000000u;
        o2.z = (uint32_t)v[3].x * 0x3C00u + (uint32_t)v[3].y * 0x3C000000u;
        o2.w = (uint32_t)v[3].z * 0x3C00u + (uint32_t)v[3].w * 0x3C000000u;
        STS128U(dstA, o1);
        STS128U(dstA + 16, o2);
    };

    // prologue: chunk 0
    {
#pragma unroll
        for (int j = 0; j < 8; j++)
            CP16(sb + S1_B0 + b_sts + j * 16, (const char*)bsrc + j * 16);
        CPCOMMIT();
        int4 v[4];
        const int4* p = (const int4*)aptr;
#pragma unroll
        for (int j = 0; j < 4; j++) v[j] = p[j];
#pragma unroll
        for (int j = 0; j < 4; j++)
            deg += v[j].x + v[j].y + v[j].z + v[j].w;
        cvt_sts(v, sb + S1_A0 + a_sts);
        CPWAITALL();
    }
    __syncthreads();

#pragma unroll 1
    for (int c = 0; c < T; c++) {
        const int buf = c & 1;
        int4 v[4];
        const bool more = (c + 1 < T);
        if (more) {
            const size_t ko = (size_t)(c + 1) * 64;
            const uint32_t bD = sb + boff[buf ^ 1] + b_sts;
            const char* bs = (const char*)(bsrc + ko);
#pragma unroll
            for (int j = 0; j < 8; j++) CP16(bD + j * 16, bs + j * 16);
            CPCOMMIT();
            const int4* p = (const int4*)(aptr + ko);
#pragma unroll
            for (int j = 0; j < 4; j++) v[j] = p[j];
        }

        const uint32_t ab = sb + aoff[buf];
        const uint32_t bb = sb + boff[buf];
#pragma unroll
        for (int ks = 0; ks < 4; ks++) {
            uint32_t A0[4], A1[4], B[16];
            LDMX4(A0, ab + a_ld + ks * 32);
            LDMX4(A1, ab + a_ld + 16 * ROWB + ks * 32);
            LDMX4(&B[0],  bb + b_ld + ks * 32);
            LDMX4(&B[4],  bb + b_ld + 16 * ROWB + ks * 32);
            LDMX4(&B[8],  bb + b_ld + 32 * ROWB + ks * 32);
            LDMX4(&B[12], bb + b_ld + 48 * ROWB + ks * 32);
#pragma unroll
            for (int t = 0; t < 4; t++) {
                MMA(acc[0][2 * t],     A0, B[4 * t + 0], B[4 * t + 2]);
                MMA(acc[0][2 * t + 1], A0, B[4 * t + 1], B[4 * t + 3]);
                MMA(acc[1][2 * t],     A1, B[4 * t + 0], B[4 * t + 2]);
                MMA(acc[1][2 * t + 1], A1, B[4 * t + 1], B[4 * t + 3]);
            }
        }

        if (more) {
#pragma unroll
            for (int j = 0; j < 4; j++)
                deg += v[j].x + v[j].y + v[j].z + v[j].w;
            cvt_sts(v, sb + aoff[buf ^ 1] + a_sts);
            CPWAITALL();
        }
        __syncthreads();
    }

    // partial degree (4 k-segments per row within a lane quad)
    deg += __shfl_xor_sync(0xffffffffu, deg, 1);
    deg += __shfl_xor_sync(0xffffffffu, deg, 2);
    if ((tid & 3) == 0)
        g_degp[z * N_NODES + rb + arow] = (float)deg;

    float* pb = g_part + ((size_t)z * N_NODES + rb) * IN_F;
#pragma unroll
    for (int mi = 0; mi < 2; mi++)
#pragma unroll
        for (int nt = 0; nt < 8; nt++) {
            const int r0 = wy * 32 + mi * 16 + (lane >> 2);
            const int cc = wx * 64 + nt * 8 + (lane & 3) * 2;
            *(float2*)(pb + (size_t)r0 * IN_F + cc) =
                make_float2(acc[mi][nt][0], acc[mi][nt][1]);
            *(float2*)(pb + (size_t)(r0 + 8) * IN_F + cc) =
                make_float2(acc[mi][nt][2], acc[mi][nt][3]);
        }
}

// =================== combine: n_x left half only ===================
__global__ void sage_combine() {
    const int id = blockIdx.x * 256 + threadIdx.x;
    const int row = id >> 6;
    const int col = (id & 63) * 4;
    const float4 p0 = *(const float4*)(g_part + (size_t)row * IN_F + col);
    const float4 p1 =
        *(const float4*)(g_part + (size_t)(N_NODES + row) * IN_F + col);
    const float inv = 1.0f / (g_degp[row] + g_degp[N_NODES + row]);
    const float4 v = make_float4((p0.x + p1.x) * inv, (p0.y + p1.y) * inv,
                                 (p0.z + p1.z) * inv, (p0.w + p1.w) * inv);
    __half2 h0 = __floats2half2_rn(v.x, v.y);
    __half2 h1 = __floats2half2_rn(v.z, v.w);
    uint2 H = make_uint2(*(uint32_t*)&h0, *(uint32_t*)&h1);
    *(uint2*)(g_nx + (size_t)row * TWO_F + col) = H;
}

// =================== Stage 2: 128x128 tiles, 2 CTAs/SM ===================
#define S2_A0   0u
#define S2_A1   18432u
#define S2_B0   36864u
#define S2_B1   55296u
#define S2_SMEM 73728

__global__ __launch_bounds__(256, 2)
void sage_out(const float* __restrict__ bias, float* __restrict__ out)
{
    extern __shared__ char smem[];
    const uint32_t sb = smem_u32(smem);
    const int tid = threadIdx.x, lane = tid & 31, wid = tid >> 5;
    const int wy = wid & 3, wx = wid >> 2;
    const int rb = blockIdx.x * 128;
    const int nb = blockIdx.y * 128;
    const int hd = blockIdx.z;
    const int T  = TWO_F / 64;

    const int arow = tid >> 1, ahalf = tid & 1;
    const __half* asrc = g_nx + (size_t)(rb + arow) * TWO_F + ahalf * 32;
    const __half* bsrc =
        g_wT + ((size_t)hd * OUT_F + nb + arow) * TWO_F + ahalf * 32;

    const uint32_t s_sts = (uint32_t)(arow * ROWB + ahalf * 64);
    const uint32_t aoff[2] = {S2_A0, S2_A1};
    const uint32_t boff[2] = {S2_B0, S2_B1};

    const uint32_t a_ld = (uint32_t)((wy * 32 + (lane & 15)) * ROWB) + (lane & 16);
    const uint32_t b_ld = (uint32_t)((wx * 64 + (lane & 15)) * ROWB) + (lane & 16);

    float acc[2][8][4];
#pragma unroll
    for (int i = 0; i < 2; i++)
#pragma unroll
        for (int j = 0; j < 8; j++)
#pragma unroll
            for (int k = 0; k < 4; k++) acc[i][j][k] = 0.0f;

    {
#pragma unroll
        for (int j = 0; j < 4; j++) {
            CP16(sb + S2_A0 + s_sts + j * 16, (const char*)asrc + j * 16);
            CP16(sb + S2_B0 + s_sts + j * 16, (const char*)bsrc + j * 16);
        }
        CPCOMMIT();
        CPWAITALL();
    }
    __syncthreads();

#pragma unroll 1
    for (int c = 0; c < T; c++) {
        const int buf = c & 1;
        if (c + 1 < T) {
            const size_t ko = (size_t)(c + 1) * 64;
            const uint32_t nbuf = buf ^ 1;
#pragma unroll
            for (int j = 0; j < 4; j++) {
                CP16(sb + aoff[nbuf] + s_sts + j * 16,
                     (const char*)(asrc + ko) + j * 16);
                CP16(sb + boff[nbuf] + s_sts + j * 16,
                     (const char*)(bsrc + ko) + j * 16);
            }
            CPCOMMIT();
        }

        const uint32_t ab = sb + aoff[buf];
        const uint32_t bb = sb + boff[buf];
#pragma unroll
        for (int ks = 0; ks < 4; ks++) {
            uint32_t A0[4], A1[4], B[16];
            LDMX4(A0, ab + a_ld + ks * 32);
            LDMX4(A1, ab + a_ld + 16 * ROWB + ks * 32);
            LDMX4(&B[0],  bb + b_ld + ks * 32);
            LDMX4(&B[4],  bb + b_ld + 16 * ROWB + ks * 32);
            LDMX4(&B[8],  bb + b_ld + 32 * ROWB + ks * 32);
            LDMX4(&B[12], bb + b_ld + 48 * ROWB + ks * 32);
#pragma unroll
            for (int t = 0; t < 4; t++) {
                MMA(acc[0][2 * t],     A0, B[4 * t + 0], B[4 * t + 2]);
                MMA(acc[0][2 * t + 1], A0, B[4 * t + 1], B[4 * t + 3]);
                MMA(acc[1][2 * t],     A1, B[4 * t + 0], B[4 * t + 2]);
                MMA(acc[1][2 * t + 1], A1, B[4 * t + 1], B[4 * t + 3]);
            }
        }
        if (c + 1 < T) CPWAITALL();
        __syncthreads();
    }

    float* ob = out + ((size_t)hd * N_NODES + rb) * OUT_F + nb;
#pragma unroll
    for (int mi = 0; mi < 2; mi++)
#pragma unroll
        for (int nt = 0; nt < 8; nt++) {
            const int r0 = wy * 32 + mi * 16 + (lane >> 2);
            const int cc = wx * 64 + nt * 8 + (lane & 3) * 2;
            const float2 bz = *(const float2*)(bias + nb + cc);
            *(float2*)(ob + (size_t)r0 * OUT_F + cc) =
                make_float2(acc[mi][nt][0] + bz.x, acc[mi][nt][1] + bz.y);
            *(float2*)(ob + (size_t)(r0 + 8) * OUT_F + cc) =
                make_float2(acc[mi][nt][2] + bz.x, acc[mi][nt][3] + bz.y);
        }
}

// =================== host launch ===================
extern "C" void kernel_launch(void* const* d_in, const int* in_sizes, int n_in,
                              void* d_out, int out_size)
{
    const float* x    = nullptr;
    const int*   adj  = nullptr;
    const float* w    = nullptr;
    const float* bias = nullptr;
    for (int i = 0; i < n_in; i++) {
        switch (in_sizes[i]) {
            case N_NODES * IN_F:      x    = (const float*)d_in[i]; break;
            case N_NODES * N_NODES:   adj  = (const int*)d_in[i];   break;
            case 3 * TWO_F * OUT_F:   w    = (const float*)d_in[i]; break;
            case OUT_F:               bias = (const float*)d_in[i]; break;
            default: break;  // scalar g
        }
    }

    cudaFuncSetAttribute(sage_agg,
                         cudaFuncAttributeMaxDynamicSharedMemorySize, S1_SMEM);
    cudaFuncSetAttribute(sage_out,
                         cudaFuncAttributeMaxDynamicSharedMemorySize, S2_SMEM);

    prep_split<<<dim3(N_NODES / 32, IN_F / 32), dim3(32, 8)>>>(x);
    prep_w<<<dim3(TWO_F / 32, OUT_F / 32, 3), dim3(32, 8)>>>(w);
    sage_agg<<<dim3(N_NODES / 64, 2), 256, S1_SMEM>>>(adj);
    sage_combine<<<(N_NODES * 64) / 256, 256>>>();
    sage_out<<<dim3(N_NODES / 128, OUT_F / 128, 3), 256, S2_SMEM>>>(
        bias, (float*)d_out);
}

// round 12
// speedup vs baseline: 1.2164x; 1.2164x over previous
#include <cuda_runtime.h>
#include <cuda_fp16.h>
#include <cstdint>

// CoreSageLayer, fp16 HMMA (sm_103-base PTX):
//   out[k] = concat((adj@x)/deg, x) @ W[k] + bias
// prep_all   : (merged) x -> xT fp16 + n_x right half;  W -> W^T fp16
// sage_agg   : part[z] = adj[:, zK:] @ xT, fp32 acc, BK=64,
//              CTA 128x256, 16 warps (32x64), 1 CTA/SM, grid (64, 2)  [R9]
// sage_combine: n_x left half = (p0+p1)/deg (fp16), 2 float4 per thread
// sage_out   : out = n_x @ W^T + bias; tile 128x128, 2 CTAs/SM       [R9]

#define N_NODES 8192
#define IN_F    256
#define TWO_F   512
#define OUT_F   256
#define ROWB    144          // 64 fp16 + 8 pad = 144 bytes

__device__ __half g_xT[(size_t)IN_F * N_NODES];
__device__ __half g_nx[(size_t)N_NODES * TWO_F];
__device__ __half g_wT[3u * OUT_F * TWO_F];
__device__ float  g_part[2ull * N_NODES * IN_F];
__device__ float  g_degp[2 * N_NODES];

__device__ __forceinline__ uint32_t smem_u32(const void* p) {
    uint32_t a;
    asm("{ .reg .u64 t; cvta.to.shared.u64 t, %1; cvt.u32.u64 %0, t; }"
        : "=r"(a) : "l"(p));
    return a;
}
#define LDMX4(r, addr) \
    asm volatile("ldmatrix.sync.aligned.m8n8.x4.shared.b16 {%0,%1,%2,%3}, [%4];" \
        : "=r"((r)[0]), "=r"((r)[1]), "=r"((r)[2]), "=r"((r)[3]) : "r"(addr))
#define MMA(d, a, b0, b1) \
    asm volatile("mma.sync.aligned.m16n8k16.row.col.f32.f16.f16.f32 " \
        "{%0,%1,%2,%3}, {%4,%5,%6,%7}, {%8,%9}, {%0,%1,%2,%3};" \
        : "+f"((d)[0]), "+f"((d)[1]), "+f"((d)[2]), "+f"((d)[3]) \
        : "r"((a)[0]), "r"((a)[1]), "r"((a)[2]), "r"((a)[3]), "r"(b0), "r"(b1))
#define CP16(dst, src) \
    asm volatile("cp.async.cg.shared.global [%0], [%1], 16;" \
        :: "r"(dst), "l"(src) : "memory")
#define CPCOMMIT()  asm volatile("cp.async.commit_group;" ::: "memory")
#define CPWAITALL() asm volatile("cp.async.wait_group 0;" ::: "memory")
#define STS128U(addr, v) \
    asm volatile("st.shared.v4.b32 [%0], {%1,%2,%3,%4};" \
        :: "r"(addr), "r"((v).x), "r"((v).y), "r"((v).z), "r"((v).w) : "memory")

// =================== merged prep: x -> xT + n_x right; W -> W^T =========
__global__ void prep_all(const float* __restrict__ x,
                         const float* __restrict__ w) {
    __shared__ float t[32][33];
    const int tx = threadIdx.x, ty = threadIdx.y;

    if (blockIdx.x < 256) {
        // ---- x part: tile (k0=node, n0=feature)
        const int k0 = blockIdx.x * 32, n0 = blockIdx.y * 32;
#pragma unroll
        for (int i = 0; i < 32; i += 8) {
            const float v = x[(size_t)(k0 + ty + i) * IN_F + n0 + tx];
            t[ty + i][tx] = v;
            g_nx[(size_t)(k0 + ty + i) * TWO_F + IN_F + n0 + tx] =
                __float2half_rn(v);
        }
        __syncthreads();
#pragma unroll
        for (int i = 0; i < 32; i += 8)
            g_xT[(size_t)(n0 + ty + i) * N_NODES + k0 + tx] =
                __float2half_rn(t[tx][ty + i]);
    } else {
        // ---- W part: tile (f0, o0), all 3 heads
        const int f0 = (blockIdx.x - 256) * 32, o0 = blockIdx.y * 32;
        for (int h = 0; h < 3; h++) {
            const float* wk = w + (size_t)h * TWO_F * OUT_F;
#pragma unroll
            for (int i = 0; i < 32; i += 8)
                t[ty + i][tx] = wk[(size_t)(f0 + ty + i) * OUT_F + o0 + tx];
            __syncthreads();
#pragma unroll
            for (int i = 0; i < 32; i += 8)
                g_wT[((size_t)h * OUT_F + o0 + ty + i) * TWO_F + f0 + tx] =
                    __float2half_rn(t[tx][ty + i]);
            __syncthreads();
        }
    }
}

// =================== Stage 1: adj aggregate (R9 config, untouched) ======
#define S1_A0   0u
#define S1_A1   18432u
#define S1_B0   36864u
#define S1_B1   73728u
#define S1_SMEM 110592

__global__ __launch_bounds__(512, 1)
void sage_agg(const int* __restrict__ adj)
{
    extern __shared__ char smem[];
    const uint32_t sb = smem_u32(smem);
    const int tid = threadIdx.x, lane = tid & 31, wid = tid >> 5;
    const int wy = wid & 3, wx = wid >> 2;
    const int rb  = blockIdx.x * 128;
    const int z   = blockIdx.y;
    const int kzb = z * (N_NODES / 2);
    const int T   = (N_NODES / 2) / 64;   // 64 chunks

    const int arow = tid >> 2, aseg = tid & 3;
    const int brow = tid >> 1, bhalf = tid & 1;

    const int*    aptr = adj + (size_t)(rb + arow) * N_NODES + kzb + aseg * 16;
    const __half* bsrc = g_xT + (size_t)brow * N_NODES + kzb + bhalf * 32;

    const uint32_t a_sts = (uint32_t)(arow * ROWB + aseg * 32);
    const uint32_t b_sts = (uint32_t)(brow * ROWB + bhalf * 64);
    const uint32_t aoff[2] = {S1_A0, S1_A1};
    const uint32_t boff[2] = {S1_B0, S1_B1};

    const uint32_t a_ld = (uint32_t)((wy * 32 + (lane & 15)) * ROWB) + (lane & 16);
    const uint32_t b_ld = (uint32_t)((wx * 64 + (lane & 15)) * ROWB) + (lane & 16);

    float acc[2][8][4];
#pragma unroll
    for (int i = 0; i < 2; i++)
#pragma unroll
        for (int j = 0; j < 8; j++)
#pragma unroll
            for (int k = 0; k < 4; k++) acc[i][j][k] = 0.0f;

    int deg = 0;

    auto cvt_sts = [&](const int4* v, uint32_t dstA) {
        uint4 o1, o2;
        o1.x = (uint32_t)v[0].x * 0x3C00u + (uint32_t)v[0].y * 0x3C000000u;
        o1.y = (uint32_t)v[0].z * 0x3C00u + (uint32_t)v[0].w * 0x3C000000u;
        o1.z = (uint32_t)v[1].x * 0x3C00u + (uint32_t)v[1].y * 0x3C000000u;
        o1.w = (uint32_t)v[1].z * 0x3C00u + (uint32_t)v[1].w * 0x3C000000u;
        o2.x = (uint32_t)v[2].x * 0x3C00u + (uint32_t)v[2].y * 0x3C000000u;
        o2.y = (uint32_t)v[2].z * 0x3C00u + (uint32_t)v[2].w * 0x3C000000u;
        o2.z = (uint32_t)v[3].x * 0x3C00u + (uint32_t)v[3].y * 0x3C000000u;
        o2.w = (uint32_t)v[3].z * 0x3C00u + (uint32_t)v[3].w * 0x3C000000u;
        STS128U(dstA, o1);
        STS128U(dstA + 16, o2);
    };

    // prologue: chunk 0
    {
#pragma unroll
        for (int j = 0; j < 4; j++)
            CP16(sb + S1_B0 + b_sts + j * 16, (const char*)bsrc + j * 16);
        CPCOMMIT();
        int4 v[4];
        const int4* p = (const int4*)aptr;
#pragma unroll
        for (int j = 0; j < 4; j++) v[j] = p[j];
#pragma unroll
        for (int j = 0; j < 4; j++)
            deg += v[j].x + v[j].y + v[j].z + v[j].w;
        cvt_sts(v, sb + S1_A0 + a_sts);
        CPWAITALL();
    }
    __syncthreads();

#pragma unroll 1
    for (int c = 0; c < T; c++) {
        const int buf = c & 1;
        int4 v[4];
        const bool more = (c + 1 < T);
        if (more) {
            const size_t ko = (size_t)(c + 1) * 64;
            const uint32_t bD = sb + boff[buf ^ 1] + b_sts;
            const char* bs = (const char*)(bsrc + ko);
#pragma unroll
            for (int j = 0; j < 4; j++) CP16(bD + j * 16, bs + j * 16);
            CPCOMMIT();
            const int4* p = (const int4*)(aptr + ko);
#pragma unroll
            for (int j = 0; j < 4; j++) v[j] = p[j];
        }

        const uint32_t ab = sb + aoff[buf];
        const uint32_t bb = sb + boff[buf];
#pragma unroll
        for (int ks = 0; ks < 4; ks++) {
            uint32_t A0[4], A1[4], B[16];
            LDMX4(A0, ab + a_ld + ks * 32);
            LDMX4(A1, ab + a_ld + 16 * ROWB + ks * 32);
            LDMX4(&B[0],  bb + b_ld + ks * 32);
            LDMX4(&B[4],  bb + b_ld + 16 * ROWB + ks * 32);
            LDMX4(&B[8],  bb + b_ld + 32 * ROWB + ks * 32);
            LDMX4(&B[12], bb + b_ld + 48 * ROWB + ks * 32);
#pragma unroll
            for (int t = 0; t < 4; t++) {
                MMA(acc[0][2 * t],     A0, B[4 * t + 0], B[4 * t + 2]);
                MMA(acc[0][2 * t + 1], A0, B[4 * t + 1], B[4 * t + 3]);
                MMA(acc[1][2 * t],     A1, B[4 * t + 0], B[4 * t + 2]);
                MMA(acc[1][2 * t + 1], A1, B[4 * t + 1], B[4 * t + 3]);
            }
        }

        if (more) {
#pragma unroll
            for (int j = 0; j < 4; j++)
                deg += v[j].x + v[j].y + v[j].z + v[j].w;
            cvt_sts(v, sb + aoff[buf ^ 1] + a_sts);
            CPWAITALL();
        }
        __syncthreads();
    }

    deg += __shfl_xor_sync(0xffffffffu, deg, 1);
    deg += __shfl_xor_sync(0xffffffffu, deg, 2);
    if ((tid & 3) == 0)
        g_degp[z * N_NODES + rb + arow] = (float)deg;

    float* pb = g_part + ((size_t)z * N_NODES + rb) * IN_F;
#pragma unroll
    for (int mi = 0; mi < 2; mi++)
#pragma unroll
        for (int nt = 0; nt < 8; nt++) {
            const int r0 = wy * 32 + mi * 16 + (lane >> 2);
            const int cc = wx * 64 + nt * 8 + (lane & 3) * 2;
            *(float2*)(pb + (size_t)r0 * IN_F + cc) =
                make_float2(acc[mi][nt][0], acc[mi][nt][1]);
            *(float2*)(pb + (size_t)(r0 + 8) * IN_F + cc) =
                make_float2(acc[mi][nt][2], acc[mi][nt][3]);
        }
}

// =================== combine: n_x left half, 2x ILP ===================
__global__ void sage_combine() {
    const int id  = blockIdx.x * 256 + threadIdx.x;  // 0 .. 8192*32
    const int row = id >> 5;
    const int c4  = id & 31;
    const float inv = 1.0f / (g_degp[row] + g_degp[N_NODES + row]);
    const float* r0 = g_part + (size_t)row * IN_F;
    const float* r1 = g_part + (size_t)(N_NODES + row) * IN_F;
#pragma unroll
    for (int j = 0; j < 2; j++) {
        const int col = (c4 + j * 32) * 4;
        const float4 p0 = *(const float4*)(r0 + col);
        const float4 p1 = *(const float4*)(r1 + col);
        const float4 v = make_float4((p0.x + p1.x) * inv, (p0.y + p1.y) * inv,
                                     (p0.z + p1.z) * inv, (p0.w + p1.w) * inv);
        __half2 h0 = __floats2half2_rn(v.x, v.y);
        __half2 h1 = __floats2half2_rn(v.z, v.w);
        uint2 H = make_uint2(*(uint32_t*)&h0, *(uint32_t*)&h1);
        *(uint2*)(g_nx + (size_t)row * TWO_F + col) = H;
    }
}

// =================== Stage 2: 128x128 tiles, 2 CTAs/SM (R9) =============
#define S2_A0   0u
#define S2_A1   18432u
#define S2_B0   36864u
#define S2_B1   55296u
#define S2_SMEM 73728

__global__ __launch_bounds__(256, 2)
void sage_out(const float* __restrict__ bias, float* __restrict__ out)
{
    extern __shared__ char smem[];
    const uint32_t sb = smem_u32(smem);
    const int tid = threadIdx.x, lane = tid & 31, wid = tid >> 5;
    const int wy = wid & 3, wx = wid >> 2;
    const int rb = blockIdx.x * 128;
    const int nb = blockIdx.y * 128;
    const int hd = blockIdx.z;
    const int T  = TWO_F / 64;

    const int arow = tid >> 1, ahalf = tid & 1;
    const __half* asrc = g_nx + (size_t)(rb + arow) * TWO_F + ahalf * 32;
    const __half* bsrc =
        g_wT + ((size_t)hd * OUT_F + nb + arow) * TWO_F + ahalf * 32;

    const uint32_t s_sts = (uint32_t)(arow * ROWB + ahalf * 64);
    const uint32_t aoff[2] = {S2_A0, S2_A1};
    const uint32_t boff[2] = {S2_B0, S2_B1};

    const uint32_t a_ld = (uint32_t)((wy * 32 + (lane & 15)) * ROWB) + (lane & 16);
    const uint32_t b_ld = (uint32_t)((wx * 64 + (lane & 15)) * ROWB) + (lane & 16);

    float acc[2][8][4];
#pragma unroll
    for (int i = 0; i < 2; i++)
#pragma unroll
        for (int j = 0; j < 8; j++)
#pragma unroll
            for (int k = 0; k < 4; k++) acc[i][j][k] = 0.0f;

    {
#pragma unroll
        for (int j = 0; j < 4; j++) {
            CP16(sb + S2_A0 + s_sts + j * 16, (const char*)asrc + j * 16);
            CP16(sb + S2_B0 + s_sts + j * 16, (const char*)bsrc + j * 16);
        }
        CPCOMMIT();
        CPWAITALL();
    }
    __syncthreads();

#pragma unroll 1
    for (int c = 0; c < T; c++) {
        const int buf = c & 1;
        if (c + 1 < T) {
            const size_t ko = (size_t)(c + 1) * 64;
            const uint32_t nbuf = buf ^ 1;
#pragma unroll
            for (int j = 0; j < 4; j++) {
                CP16(sb + aoff[nbuf] + s_sts + j * 16,
                     (const char*)(asrc + ko) + j * 16);
                CP16(sb + boff[nbuf] + s_sts + j * 16,
                     (const char*)(bsrc + ko) + j * 16);
            }
            CPCOMMIT();
        }

        const uint32_t ab = sb + aoff[buf];
        const uint32_t bb = sb + boff[buf];
#pragma unroll
        for (int ks = 0; ks < 4; ks++) {
            uint32_t A0[4], A1[4], B[16];
            LDMX4(A0, ab + a_ld + ks * 32);
            LDMX4(A1, ab + a_ld + 16 * ROWB + ks * 32);
            LDMX4(&B[0],  bb + b_ld + ks * 32);
            LDMX4(&B[4],  bb + b_ld + 16 * ROWB + ks * 32);
            LDMX4(&B[8],  bb + b_ld + 32 * ROWB + ks * 32);
            LDMX4(&B[12], bb + b_ld + 48 * ROWB + ks * 32);
#pragma unroll
            for (int t = 0; t < 4; t++) {
                MMA(acc[0][2 * t],     A0, B[4 * t + 0], B[4 * t + 2]);
                MMA(acc[0][2 * t + 1], A0, B[4 * t + 1], B[4 * t + 3]);
                MMA(acc[1][2 * t],     A1, B[4 * t + 0], B[4 * t + 2]);
                MMA(acc[1][2 * t + 1], A1, B[4 * t + 1], B[4 * t + 3]);
            }
        }
        if (c + 1 < T) CPWAITALL();
        __syncthreads();
    }

    float* ob = out + ((size_t)hd * N_NODES + rb) * OUT_F + nb;
#pragma unroll
    for (int mi = 0; mi < 2; mi++)
#pragma unroll
        for (int nt = 0; nt < 8; nt++) {
            const int r0 = wy * 32 + mi * 16 + (lane >> 2);
            const int cc = wx * 64 + nt * 8 + (lane & 3) * 2;
            const float2 bz = *(const float2*)(bias + nb + cc);
            *(float2*)(ob + (size_t)r0 * OUT_F + cc) =
                make_float2(acc[mi][nt][0] + bz.x, acc[mi][nt][1] + bz.y);
            *(float2*)(ob + (size_t)(r0 + 8) * OUT_F + cc) =
                make_float2(acc[mi][nt][2] + bz.x, acc[mi][nt][3] + bz.y);
        }
}

// =================== host launch ===================
extern "C" void kernel_launch(void* const* d_in, const int* in_sizes, int n_in,
                              void* d_out, int out_size)
{
    const float* x    = nullptr;
    const int*   adj  = nullptr;
    const float* w    = nullptr;
    const float* bias = nullptr;
    for (int i = 0; i < n_in; i++) {
        switch (in_sizes[i]) {
            case N_NODES * IN_F:      x    = (const float*)d_in[i]; break;
            case N_NODES * N_NODES:   adj  = (const int*)d_in[i];   break;
            case 3 * TWO_F * OUT_F:   w    = (const float*)d_in[i]; break;
            case OUT_F:               bias = (const float*)d_in[i]; break;
            default: break;  // scalar g
        }
    }

    cudaFuncSetAttribute(sage_agg,
                         cudaFuncAttributeMaxDynamicSharedMemorySize, S1_SMEM);
    cudaFuncSetAttribute(sage_out,
                         cudaFuncAttributeMaxDynamicSharedMemorySize, S2_SMEM);

    prep_all<<<dim3(256 + TWO_F / 32, IN_F / 32), dim3(32, 8)>>>(x, w);
    sage_agg<<<dim3(N_NODES / 128, 2), 512, S1_SMEM>>>(adj);
    sage_combine<<<(N_NODES * 32) / 256, 256>>>();
    sage_out<<<dim3(N_NODES / 128, OUT_F / 128, 3), 256, S2_SMEM>>>(
        bias, (float*)d_out);
}

// round 15
// speedup vs baseline: 1.2621x; 1.0375x over previous
#include <cuda_runtime.h>
#include <cuda_fp16.h>
#include <cstdint>

// CoreSageLayer, fp16 HMMA (sm_103-base PTX):
//   out[k] = concat((adj@x)/deg, x) @ W[k] + bias
// prep_all   : (merged) x -> xT fp16 + n_x right half;  W -> W^T fp16
// sage_agg   : part[z] = adj[:, zK:] @ xT, fp32 acc, BK=64,
//              CTA 128x256, 16 warps (32x64), B triple-buffered (depth-2)
// sage_combine: n_x left half = (p0+p1)/deg (fp16), 2 float4 per thread
// sage_out   : out = n_x @ W^T + bias; 128x128, 2 CTAs/SM, A+B triple-buf

#define N_NODES 8192
#define IN_F    256
#define TWO_F   512
#define OUT_F   256
#define ROWB    144          // 64 fp16 + 8 pad = 144 bytes

__device__ __half g_xT[(size_t)IN_F * N_NODES];
__device__ __half g_nx[(size_t)N_NODES * TWO_F];
__device__ __half g_wT[3u * OUT_F * TWO_F];
__device__ float  g_part[2ull * N_NODES * IN_F];
__device__ float  g_degp[2 * N_NODES];

__device__ __forceinline__ uint32_t smem_u32(const void* p) {
    uint32_t a;
    asm("{ .reg .u64 t; cvta.to.shared.u64 t, %1; cvt.u32.u64 %0, t; }"
        : "=r"(a) : "l"(p));
    return a;
}
#define LDMX4(r, addr) \
    asm volatile("ldmatrix.sync.aligned.m8n8.x4.shared.b16 {%0,%1,%2,%3}, [%4];" \
        : "=r"((r)[0]), "=r"((r)[1]), "=r"((r)[2]), "=r"((r)[3]) : "r"(addr))
#define MMA(d, a, b0, b1) \
    asm volatile("mma.sync.aligned.m16n8k16.row.col.f32.f16.f16.f32 " \
        "{%0,%1,%2,%3}, {%4,%5,%6,%7}, {%8,%9}, {%0,%1,%2,%3};" \
        : "+f"((d)[0]), "+f"((d)[1]), "+f"((d)[2]), "+f"((d)[3]) \
        : "r"((a)[0]), "r"((a)[1]), "r"((a)[2]), "r"((a)[3]), "r"(b0), "r"(b1))
#define CP16(dst, src) \
    asm volatile("cp.async.cg.shared.global [%0], [%1], 16;" \
        :: "r"(dst), "l"(src) : "memory")
#define CPCOMMIT()  asm volatile("cp.async.commit_group;" ::: "memory")
#define CPWAIT1()   asm volatile("cp.async.wait_group 1;" ::: "memory")
#define STS128U(addr, v) \
    asm volatile("st.shared.v4.b32 [%0], {%1,%2,%3,%4};" \
        :: "r"(addr), "r"((v).x), "r"((v).y), "r"((v).z), "r"((v).w) : "memory")

// =================== merged prep: x -> xT + n_x right; W -> W^T =========
__global__ void prep_all(const float* __restrict__ x,
                         const float* __restrict__ w) {
    __shared__ float t[32][33];
    const int tx = threadIdx.x, ty = threadIdx.y;

    if (blockIdx.x < 256) {
        const int k0 = blockIdx.x * 32, n0 = blockIdx.y * 32;
#pragma unroll
        for (int i = 0; i < 32; i += 8) {
            const float v = x[(size_t)(k0 + ty + i) * IN_F + n0 + tx];
            t[ty + i][tx] = v;
            g_nx[(size_t)(k0 + ty + i) * TWO_F + IN_F + n0 + tx] =
                __float2half_rn(v);
        }
        __syncthreads();
#pragma unroll
        for (int i = 0; i < 32; i += 8)
            g_xT[(size_t)(n0 + ty + i) * N_NODES + k0 + tx] =
                __float2half_rn(t[tx][ty + i]);
    } else {
        const int f0 = (blockIdx.x - 256) * 32, o0 = blockIdx.y * 32;
        for (int h = 0; h < 3; h++) {
            const float* wk = w + (size_t)h * TWO_F * OUT_F;
#pragma unroll
            for (int i = 0; i < 32; i += 8)
                t[ty + i][tx] = wk[(size_t)(f0 + ty + i) * OUT_F + o0 + tx];
            __syncthreads();
#pragma unroll
            for (int i = 0; i < 32; i += 8)
                g_wT[((size_t)h * OUT_F + o0 + ty + i) * TWO_F + f0 + tx] =
                    __float2half_rn(t[tx][ty + i]);
            __syncthreads();
        }
    }
}

// =================== Stage 1: adj aggregate (B depth-2 prefetch) ========
#define S1_A0   0u
#define S1_A1   18432u
#define S1_B0   36864u
#define S1_B1   73728u
#define S1_B2   110592u
#define S1_SMEM 147456

__global__ __launch_bounds__(512, 1)
void sage_agg(const int* __restrict__ adj)
{
    extern __shared__ char smem[];
    const uint32_t sb = smem_u32(smem);
    const int tid = threadIdx.x, lane = tid & 31, wid = tid >> 5;
    const int wy = wid & 3, wx = wid >> 2;
    const int rb  = blockIdx.x * 128;
    const int z   = blockIdx.y;
    const int kzb = z * (N_NODES / 2);
    const int T   = (N_NODES / 2) / 64;   // 64 chunks

    const int arow = tid >> 2, aseg = tid & 3;
    const int brow = tid >> 1, bhalf = tid & 1;

    const int*    aptr = adj + (size_t)(rb + arow) * N_NODES + kzb + aseg * 16;
    const __half* bsrc = g_xT + (size_t)brow * N_NODES + kzb + bhalf * 32;

    const uint32_t a_sts = (uint32_t)(arow * ROWB + aseg * 32);
    const uint32_t b_sts = (uint32_t)(brow * ROWB + bhalf * 64);
    const uint32_t aoff[2] = {S1_A0, S1_A1};
    const uint32_t boff[3] = {S1_B0, S1_B1, S1_B2};

    const uint32_t a_ld = (uint32_t)((wy * 32 + (lane & 15)) * ROWB) + (lane & 16);
    const uint32_t b_ld = (uint32_t)((wx * 64 + (lane & 15)) * ROWB) + (lane & 16);

    float acc[2][8][4];
#pragma unroll
    for (int i = 0; i < 2; i++)
#pragma unroll
        for (int j = 0; j < 8; j++)
#pragma unroll
            for (int k = 0; k < 4; k++) acc[i][j][k] = 0.0f;

    int deg = 0;

    auto cvt_sts = [&](const int4* v, uint32_t dstA) {
        uint4 o1, o2;
        o1.x = (uint32_t)v[0].x * 0x3C00u + (uint32_t)v[0].y * 0x3C000000u;
        o1.y = (uint32_t)v[0].z * 0x3C00u + (uint32_t)v[0].w * 0x3C000000u;
        o1.z = (uint32_t)v[1].x * 0x3C00u + (uint32_t)v[1].y * 0x3C000000u;
        o1.w = (uint32_t)v[1].z * 0x3C00u + (uint32_t)v[1].w * 0x3C000000u;
        o2.x = (uint32_t)v[2].x * 0x3C00u + (uint32_t)v[2].y * 0x3C000000u;
        o2.y = (uint32_t)v[2].z * 0x3C00u + (uint32_t)v[2].w * 0x3C000000u;
        o2.z = (uint32_t)v[3].x * 0x3C00u + (uint32_t)v[3].y * 0x3C000000u;
        o2.w = (uint32_t)v[3].z * 0x3C00u + (uint32_t)v[3].w * 0x3C000000u;
        STS128U(dstA, o1);
        STS128U(dstA + 16, o2);
    };

    // ---- prologue: B chunks 0 and 1 in flight; A chunk 0 in smem
    {
#pragma unroll
        for (int j = 0; j < 4; j++)
            CP16(sb + S1_B0 + b_sts + j * 16, (const char*)bsrc + j * 16);
        CPCOMMIT();                                   // group: chunk 0
        const char* bs1 = (const char*)(bsrc + 64);
#pragma unroll
        for (int j = 0; j < 4; j++)
            CP16(sb + S1_B1 + b_sts + j * 16, bs1 + j * 16);
        CPCOMMIT();                                   // group: chunk 1
        int4 v[4];
        const int4* p = (const int4*)aptr;
#pragma unroll
        for (int j = 0; j < 4; j++) v[j] = p[j];
#pragma unroll
        for (int j = 0; j < 4; j++)
            deg += v[j].x + v[j].y + v[j].z + v[j].w;
        cvt_sts(v, sb + S1_A0 + a_sts);
        CPWAIT1();                                    // chunk-0 B resident
    }
    __syncthreads();

    int bb = 0;                                       // B buffer index = c%3
#pragma unroll 1
    for (int c = 0; c < T; c++) {
        int4 v[4];
        if (c + 2 < T) {                              // B for c+2, depth 2
            const size_t ko = (size_t)(c + 2) * 64;
            const int nb = (bb + 2 >= 3) ? bb - 1 : bb + 2;
            const uint32_t bD = sb + boff[nb] + b_sts;
            const char* bs = (const char*)(bsrc + ko);
#pragma unroll
            for (int j = 0; j < 4; j++) CP16(bD + j * 16, bs + j * 16);
        }
        CPCOMMIT();                                   // always: uniform count
        const bool morea = (c + 1 < T);
        if (morea) {
            const int4* p = (const int4*)(aptr + (size_t)(c + 1) * 64);
#pragma unroll
            for (int j = 0; j < 4; j++) v[j] = p[j];
        }

        const uint32_t ab = sb + aoff[c & 1];
        const uint32_t bbse = sb + boff[bb];
#pragma unroll
        for (int ks = 0; ks < 4; ks++) {
            uint32_t A0[4], A1[4], B[16];
            LDMX4(A0, ab + a_ld + ks * 32);
            LDMX4(A1, ab + a_ld + 16 * ROWB + ks * 32);
            LDMX4(&B[0],  bbse + b_ld + ks * 32);
            LDMX4(&B[4],  bbse + b_ld + 16 * ROWB + ks * 32);
            LDMX4(&B[8],  bbse + b_ld + 32 * ROWB + ks * 32);
            LDMX4(&B[12], bbse + b_ld + 48 * ROWB + ks * 32);
#pragma unroll
            for (int t = 0; t < 4; t++) {
                MMA(acc[0][2 * t],     A0, B[4 * t + 0], B[4 * t + 2]);
                MMA(acc[0][2 * t + 1], A0, B[4 * t + 1], B[4 * t + 3]);
                MMA(acc[1][2 * t],     A1, B[4 * t + 0], B[4 * t + 2]);
                MMA(acc[1][2 * t + 1], A1, B[4 * t + 1], B[4 * t + 3]);
            }
        }

        if (morea) {
#pragma unroll
            for (int j = 0; j < 4; j++)
                deg += v[j].x + v[j].y + v[j].z + v[j].w;
            cvt_sts(v, sb + aoff[(c + 1) & 1] + a_sts);
        }
        CPWAIT1();                                    // chunk c+1 B resident
        __syncthreads();
        bb = (bb == 2) ? 0 : bb + 1;
    }

    deg += __shfl_xor_sync(0xffffffffu, deg, 1);
    deg += __shfl_xor_sync(0xffffffffu, deg, 2);
    if ((tid & 3) == 0)
        g_degp[z * N_NODES + rb + arow] = (float)deg;

    float* pb = g_part + ((size_t)z * N_NODES + rb) * IN_F;
#pragma unroll
    for (int mi = 0; mi < 2; mi++)
#pragma unroll
        for (int nt = 0; nt < 8; nt++) {
            const int r0 = wy * 32 + mi * 16 + (lane >> 2);
            const int cc = wx * 64 + nt * 8 + (lane & 3) * 2;
            *(float2*)(pb + (size_t)r0 * IN_F + cc) =
                make_float2(acc[mi][nt][0], acc[mi][nt][1]);
            *(float2*)(pb + (size_t)(r0 + 8) * IN_F + cc) =
                make_float2(acc[mi][nt][2], acc[mi][nt][3]);
        }
}

// =================== combine: n_x left half, 2x ILP ===================
__global__ void sage_combine() {
    const int id  = blockIdx.x * 256 + threadIdx.x;
    const int row = id >> 5;
    const int c4  = id & 31;
    const float inv = 1.0f / (g_degp[row] + g_degp[N_NODES + row]);
    const float* r0 = g_part + (size_t)row * IN_F;
    const float* r1 = g_part + (size_t)(N_NODES + row) * IN_F;
#pragma unroll
    for (int j = 0; j < 2; j++) {
        const int col = (c4 + j * 32) * 4;
        const float4 p0 = *(const float4*)(r0 + col);
        const float4 p1 = *(const float4*)(r1 + col);
        const float4 v = make_float4((p0.x + p1.x) * inv, (p0.y + p1.y) * inv,
                                     (p0.z + p1.z) * inv, (p0.w + p1.w) * inv);
        __half2 h0 = __floats2half2_rn(v.x, v.y);
        __half2 h1 = __floats2half2_rn(v.z, v.w);
        uint2 H = make_uint2(*(uint32_t*)&h0, *(uint32_t*)&h1);
        *(uint2*)(g_nx + (size_t)row * TWO_F + col) = H;
    }
}

// =================== Stage 2: 128x128, A+B depth-2 prefetch =============
#define S2_A0   0u
#define S2_A1   18432u
#define S2_A2   36864u
#define S2_B0   55296u
#define S2_B1   73728u
#define S2_B2   92160u
#define S2_SMEM 110592

__global__ __launch_bounds__(256, 2)
void sage_out(const float* __restrict__ bias, float* __restrict__ out)
{
    extern __shared__ char smem[];
    const uint32_t sb = smem_u32(smem);
    const int tid = threadIdx.x, lane = tid & 31, wid = tid >> 5;
    const int wy = wid & 3, wx = wid >> 2;
    const int rb = blockIdx.x * 128;
    const int nb = blockIdx.y * 128;
    const int hd = blockIdx.z;
    const int T  = TWO_F / 64;                        // 8 chunks

    const int arow = tid >> 1, ahalf = tid & 1;
    const __half* asrc = g_nx + (size_t)(rb + arow) * TWO_F + ahalf * 32;
    const __half* bsrc =
        g_wT + ((size_t)hd * OUT_F + nb + arow) * TWO_F + ahalf * 32;

    const uint32_t s_sts = (uint32_t)(arow * ROWB + ahalf * 64);
    const uint32_t aoff[3] = {S2_A0, S2_A1, S2_A2};
    const uint32_t boff[3] = {S2_B0, S2_B1, S2_B2};

    const uint32_t a_ld = (uint32_t)((wy * 32 + (lane & 15)) * ROWB) + (lane & 16);
    const uint32_t b_ld = (uint32_t)((wx * 64 + (lane & 15)) * ROWB) + (lane & 16);

    float acc[2][8][4];
#pragma unroll
    for (int i = 0; i < 2; i++)
#pragma unroll
        for (int j = 0; j < 8; j++)
#pragma unroll
            for (int k = 0; k < 4; k++) acc[i][j][k] = 0.0f;

    // ---- prologue: chunks 0 and 1 in flight
    {
#pragma unroll
        for (int j = 0; j < 4; j++) {
            CP16(sb + S2_A0 + s_sts + j * 16, (const char*)asrc + j * 16);
            CP16(sb + S2_B0 + s_sts + j * 16, (const char*)bsrc + j * 16);
        }
        CPCOMMIT();
        const char* as1 = (const char*)(asrc + 64);
        const char* bs1 = (const char*)(bsrc + 64);
#pragma unroll
        for (int j = 0; j < 4; j++) {
            CP16(sb + S2_A1 + s_sts + j * 16, as1 + j * 16);
            CP16(sb + S2_B1 + s_sts + j * 16, bs1 + j * 16);
        }
        CPCOMMIT();
        CPWAIT1();
    }
    __syncthreads();

    int bb = 0;
#pragma unroll 1
    for (int c = 0; c < T; c++) {
        if (c + 2 < T) {
            const size_t ko = (size_t)(c + 2) * 64;
            const int nbuf = (bb + 2 >= 3) ? bb - 1 : bb + 2;
#pragma unroll
            for (int j = 0; j < 4; j++) {
                CP16(sb + aoff[nbuf] + s_sts + j * 16,
                     (const char*)(asrc + ko) + j * 16);
                CP16(sb + boff[nbuf] + s_sts + j * 16,
                     (const char*)(bsrc + ko) + j * 16);
            }
        }
        CPCOMMIT();

        const uint32_t ab = sb + aoff[bb];
        const uint32_t bbse = sb + boff[bb];
#pragma unroll
        for (int ks = 0; ks < 4; ks++) {
            uint32_t A0[4], A1[4], B[16];
            LDMX4(A0, ab + a_ld + ks * 32);
            LDMX4(A1, ab + a_ld + 16 * ROWB + ks * 32);
            LDMX4(&B[0],  bbse + b_ld + ks * 32);
            LDMX4(&B[4],  bbse + b_ld + 16 * ROWB + ks * 32);
            LDMX4(&B[8],  bbse + b_ld + 32 * ROWB + ks * 32);
            LDMX4(&B[12], bbse + b_ld + 48 * ROWB + ks * 32);
#pragma unroll
            for (int t = 0; t < 4; t++) {
                MMA(acc[0][2 * t],     A0, B[4 * t + 0], B[4 * t + 2]);
                MMA(acc[0][2 * t + 1], A0, B[4 * t + 1], B[4 * t + 3]);
                MMA(acc[1][2 * t],     A1, B[4 * t + 0], B[4 * t + 2]);
                MMA(acc[1][2 * t + 1], A1, B[4 * t + 1], B[4 * t + 3]);
            }
        }
        CPWAIT1();
        __syncthreads();
        bb = (bb == 2) ? 0 : bb + 1;
    }

    float* ob = out + ((size_t)hd * N_NODES + rb) * OUT_F + nb;
#pragma unroll
    for (int mi = 0; mi < 2; mi++)
#pragma unroll
        for (int nt = 0; nt < 8; nt++) {
            const int r0 = wy * 32 + mi * 16 + (lane >> 2);
            const int cc = wx * 64 + nt * 8 + (lane & 3) * 2;
            const float2 bz = *(const float2*)(bias + nb + cc);
            *(float2*)(ob + (size_t)r0 * OUT_F + cc) =
                make_float2(acc[mi][nt][0] + bz.x, acc[mi][nt][1] + bz.y);
            *(float2*)(ob + (size_t)(r0 + 8) * OUT_F + cc) =
                make_float2(acc[mi][nt][2] + bz.x, acc[mi][nt][3] + bz.y);
        }
}

// =================== host launch ===================
extern "C" void kernel_launch(void* const* d_in, const int* in_sizes, int n_in,
                              void* d_out, int out_size)
{
    const float* x    = nullptr;
    const int*   adj  = nullptr;
    const float* w    = nullptr;
    const float* bias = nullptr;
    for (int i = 0; i < n_in; i++) {
        switch (in_sizes[i]) {
            case N_NODES * IN_F:      x    = (const float*)d_in[i]; break;
            case N_NODES * N_NODES:   adj  = (const int*)d_in[i];   break;
            case 3 * TWO_F * OUT_F:   w    = (const float*)d_in[i]; break;
            case OUT_F:               bias = (const float*)d_in[i]; break;
            default: break;  // scalar g
        }
    }

    cudaFuncSetAttribute(sage_agg,
                         cudaFuncAttributeMaxDynamicSharedMemorySize, S1_SMEM);
    cudaFuncSetAttribute(sage_out,
                         cudaFuncAttributeMaxDynamicSharedMemorySize, S2_SMEM);

    prep_all<<<dim3(256 + TWO_F / 32, IN_F / 32), dim3(32, 8)>>>(x, w);
    sage_agg<<<dim3(N_NODES / 128, 2), 512, S1_SMEM>>>(adj);
    sage_combine<<<(N_NODES * 32) / 256, 256>>>();
    sage_out<<<dim3(N_NODES / 128, OUT_F / 128, 3), 256, S2_SMEM>>>(
        bias, (float*)d_out);
}